// round 2
// baseline (speedup 1.0000x reference)
#include <cuda_runtime.h>
#include <cuda_bf16.h>
#include <cstdint>

// SpMM (COO, rows sorted): out[r,:] = sum_{e: rows[e]==r} vals[e] * embeds[cols[e],:]
// N=50000, E=800000, D=64, fp32.
// NOTE: reference is JAX with x64 disabled -> rows/cols are int32 on device.
//
// Strategy: warp-per-chunk segmented reduction over sorted rows.
//  - each warp owns E_PER_WARP consecutive edges
//  - lane l accumulates features {2l, 2l+1} as float2 (warp = full D=64 row,
//    256B coalesced gather per edge, L2-resident: embeds = 12.8MB << 126MB L2)
//  - register accumulation while row id constant; atomicAdd flush only at
//    row boundaries

#define D_FEAT        64
#define E_PER_WARP    128
#define WARPS_PER_CTA 8
#define CTA_THREADS   (WARPS_PER_CTA * 32)

__global__ void zero_kernel(float* __restrict__ out, int n) {
    int i = blockIdx.x * blockDim.x + threadIdx.x;
    int stride = gridDim.x * blockDim.x;
    for (; i < n; i += stride) out[i] = 0.0f;
}

__global__ __launch_bounds__(CTA_THREADS)
void spmm_kernel(const int*   __restrict__ rows,
                 const int*   __restrict__ cols,
                 const float* __restrict__ vals,
                 const float* __restrict__ embeds,
                 float*       __restrict__ out,
                 int n_edges)
{
    __shared__ int   s_row[WARPS_PER_CTA][E_PER_WARP];
    __shared__ int   s_col[WARPS_PER_CTA][E_PER_WARP];
    __shared__ float s_val[WARPS_PER_CTA][E_PER_WARP];

    const int warp = threadIdx.x >> 5;
    const int lane = threadIdx.x & 31;

    const int base = (blockIdx.x * WARPS_PER_CTA + warp) * E_PER_WARP;
    if (base >= n_edges) return;
    const int n = min(E_PER_WARP, n_edges - base);

    // Warp-cooperative staging of edge metadata into shared (coalesced LDG,
    // later read via broadcast LDS — conflict-free).
    for (int i = lane; i < n; i += 32) {
        s_row[warp][i] = rows[base + i];
        s_col[warp][i] = cols[base + i];
        s_val[warp][i] = vals[base + i];
    }
    __syncwarp();

    const float2* __restrict__ emb2 = (const float2*)embeds;

    float accx = 0.0f, accy = 0.0f;
    int cur_row = s_row[warp][0];

    for (int i = 0; i < n; i++) {
        const int r = s_row[warp][i];        // uniform across warp
        if (r != cur_row) {                  // uniform branch
            atomicAdd(&out[cur_row * D_FEAT + 2 * lane],     accx);
            atomicAdd(&out[cur_row * D_FEAT + 2 * lane + 1], accy);
            accx = 0.0f; accy = 0.0f;
            cur_row = r;
        }
        const float  v = s_val[warp][i];
        const float2 e = emb2[s_col[warp][i] * (D_FEAT / 2) + lane];
        accx = fmaf(v, e.x, accx);
        accy = fmaf(v, e.y, accy);
    }
    atomicAdd(&out[cur_row * D_FEAT + 2 * lane],     accx);
    atomicAdd(&out[cur_row * D_FEAT + 2 * lane + 1], accy);
}

extern "C" void kernel_launch(void* const* d_in, const int* in_sizes, int n_in,
                              void* d_out, int out_size)
{
    const int*   rows   = (const int*)d_in[0];
    const int*   cols   = (const int*)d_in[1];
    const float* vals   = (const float*)d_in[2];
    const float* embeds = (const float*)d_in[3];
    float*       out    = (float*)d_out;

    const int n_edges = in_sizes[0];

    // 1) zero the (poisoned) output — rows with no edges must be exactly 0
    zero_kernel<<<592, 256>>>(out, out_size);

    // 2) segmented SpMM
    const int n_warp_chunks = (n_edges + E_PER_WARP - 1) / E_PER_WARP;
    const int blocks = (n_warp_chunks + WARPS_PER_CTA - 1) / WARPS_PER_CTA;
    spmm_kernel<<<blocks, CTA_THREADS>>>(rows, cols, vals, embeds, out, n_edges);
}